// round 6
// baseline (speedup 1.0000x reference)
#include <cuda_runtime.h>

// ---------------------------------------------------------------------------
// SlidingWindowAttention: x->QKV proj -> windowed attention -> out proj
// B=2, S=2048, H=16, hd=64, D=1024, window=512. All fp32.
// ---------------------------------------------------------------------------

constexpr int BB  = 2;
constexpr int SS  = 2048;
constexpr int NH  = 16;
constexpr int HDm = 64;
constexpr int DM  = 1024;      // NH*HDm
constexpr int ND3 = 3072;      // 3*DM
constexpr int WIN = 512;
constexpr int MT  = BB * SS;   // 4096 rows

// Scratch (device globals: allocation-free)
__device__ float g_Q[BB * NH * SS * HDm];
__device__ float g_K[BB * NH * SS * HDm];
__device__ float g_V[BB * NH * SS * HDm];
__device__ float g_AO[BB * SS * DM];

// ---------------------------------------------------------------------------
// SGEMM: C[M=4096][N] = A[4096][1024] @ W[1024][N] + bias
// BM=BN=128, BK=8, 256 threads, 8x8 per-thread micro-tile.
// EPI==0: A = x param, scatter into g_Q/g_K/g_V (qkv layout (b,h,s,d))
// EPI==1: A = g_AO, plain write to Cout + bias
// ---------------------------------------------------------------------------
template <int N, int EPI>
__global__ __launch_bounds__(256) void gemm_kernel(const float* __restrict__ A,
                                                   const float* __restrict__ Bmat,
                                                   const float* __restrict__ bias,
                                                   float* __restrict__ Cout)
{
    __shared__ float As[8][132];   // transposed A tile, padded (STS conflict-free)
    __shared__ float Bs[8][128];

    const int tid = threadIdx.x;
    const int n0  = blockIdx.x * 128;
    const int m0  = blockIdx.y * 128;
    const int ty  = tid >> 4;          // 0..15 -> M rows ty*8..+7
    const int tx  = tid & 15;          // 0..15 -> N cols tx*8..+7
    const int arow = tid >> 1;         // 0..127
    const int acol = (tid & 1) * 4;    // 0 or 4
    const int brow = tid >> 5;         // 0..7
    const int bcol = (tid & 31) * 4;   // 0..124

    const float* Ap = (EPI == 0) ? A : g_AO;

    float acc[8][8];
#pragma unroll
    for (int i = 0; i < 8; i++)
#pragma unroll
        for (int j = 0; j < 8; j++) acc[i][j] = 0.f;

    const float* aptr = Ap + (m0 + arow) * DM + acol;
    const float* bptr = Bmat + brow * N + n0 + bcol;

    for (int k0 = 0; k0 < DM; k0 += 8) {
        float4 a4 = *(const float4*)(aptr + k0);
        As[acol + 0][arow] = a4.x;
        As[acol + 1][arow] = a4.y;
        As[acol + 2][arow] = a4.z;
        As[acol + 3][arow] = a4.w;
        float4 b4 = *(const float4*)(bptr + k0 * N);
        *(float4*)&Bs[brow][bcol] = b4;
        __syncthreads();

#pragma unroll
        for (int k = 0; k < 8; k++) {
            float af[8], bf[8];
            *(float4*)&af[0] = *(const float4*)&As[k][ty * 8];
            *(float4*)&af[4] = *(const float4*)&As[k][ty * 8 + 4];
            *(float4*)&bf[0] = *(const float4*)&Bs[k][tx * 8];
            *(float4*)&bf[4] = *(const float4*)&Bs[k][tx * 8 + 4];
#pragma unroll
            for (int i = 0; i < 8; i++)
#pragma unroll
                for (int j = 0; j < 8; j++)
                    acc[i][j] = fmaf(af[i], bf[j], acc[i][j]);
        }
        __syncthreads();
    }

    if (EPI == 0) {
        // n0 is a multiple of 128 and 1024%128==0 -> 'which' uniform per CTA
        const int which = n0 >> 10;
        float* dst = (which == 0) ? g_Q : (which == 1) ? g_K : g_V;
        const int n_base = n0 + tx * 8;       // thread's 8 cols stay inside one head
        const int rem = n_base & (DM - 1);
        const int hh  = rem >> 6;
        const int d0  = rem & 63;
#pragma unroll
        for (int i = 0; i < 8; i++) {
            const int m  = m0 + ty * 8 + i;
            const int bb = m >> 11;           // /SS
            const int ss = m & (SS - 1);
            float* row = dst + ((bb * NH + hh) * SS + ss) * HDm + d0;
#pragma unroll
            for (int j = 0; j < 8; j++)
                row[j] = acc[i][j] + bias[n_base + j];
        }
    } else {
        const int n_base = n0 + tx * 8;
        float b0 = bias[n_base + 0], b1 = bias[n_base + 1], b2 = bias[n_base + 2], b3 = bias[n_base + 3];
        float b4v = bias[n_base + 4], b5 = bias[n_base + 5], b6 = bias[n_base + 6], b7 = bias[n_base + 7];
#pragma unroll
        for (int i = 0; i < 8; i++) {
            const int m = m0 + ty * 8 + i;
            float4 v0, v1;
            v0.x = acc[i][0] + b0; v0.y = acc[i][1] + b1;
            v0.z = acc[i][2] + b2; v0.w = acc[i][3] + b3;
            v1.x = acc[i][4] + b4v; v1.y = acc[i][5] + b5;
            v1.z = acc[i][6] + b6; v1.w = acc[i][7] + b7;
            *(float4*)&Cout[m * N + n_base]     = v0;
            *(float4*)&Cout[m * N + n_base + 4] = v1;
        }
    }
}

// ---------------------------------------------------------------------------
// Windowed flash attention. One CTA per (64-query tile, head, batch).
// 256 threads = 16x16; each thread owns a 4q x 4col micro-tile.
// Smem layouts chosen so inner loops are pure LDS.128:
//   Qst[kd][q], Kst[kd][j], Vs[k][dh], Pst[k][q]   (row pitch 68 floats)
// ---------------------------------------------------------------------------
constexpr int PITCH = 68;
constexpr int ATTN_SMEM_BYTES = 4 * 64 * PITCH * (int)sizeof(float);  // 69632

__global__ __launch_bounds__(256) void attn_kernel()
{
    extern __shared__ float smf[];
    float* Qst = smf;
    float* Kst = Qst + 64 * PITCH;
    float* Vs  = Kst + 64 * PITCH;
    float* Pst = Vs  + 64 * PITCH;

    const int tid = threadIdx.x;
    const int ty  = tid >> 4;     // query group: rows ty*4..+3
    const int tx  = tid & 15;     // col group: cols tx*4..+3
    const int q0  = blockIdx.x * 64;
    const int h   = blockIdx.y;
    const int b   = blockIdx.z;

    const float* Qg = g_Q + (size_t)(b * NH + h) * SS * HDm;
    const float* Kg = g_K + (size_t)(b * NH + h) * SS * HDm;
    const float* Vg = g_V + (size_t)(b * NH + h) * SS * HDm;

    // Load Q tile (64 x 64) transposed to kd-major
    for (int t = tid; t < 1024; t += 256) {
        const int r = t >> 4;
        const int c = (t & 15) * 4;
        float4 v = *(const float4*)(Qg + (q0 + r) * HDm + c);
        Qst[(c + 0) * PITCH + r] = v.x;
        Qst[(c + 1) * PITCH + r] = v.y;
        Qst[(c + 2) * PITCH + r] = v.z;
        Qst[(c + 3) * PITCH + r] = v.w;
    }

    float m_prev[4], lsum[4], o[4][4];
#pragma unroll
    for (int i = 0; i < 4; i++) {
        m_prev[i] = -1e30f;
        lsum[i] = 0.f;
#pragma unroll
        for (int j = 0; j < 4; j++) o[i][j] = 0.f;
    }

    const int kb_start = (q0 >= WIN) ? ((q0 - (WIN - 1)) >> 6) : 0;
    const int kb_end   = q0 >> 6;    // inclusive

    __syncthreads();

    for (int kb = kb_start; kb <= kb_end; kb++) {
        const float* Kb = Kg + kb * 64 * HDm;
        const float* Vb = Vg + kb * 64 * HDm;
        for (int t = tid; t < 1024; t += 256) {
            const int r = t >> 4;
            const int c = (t & 15) * 4;
            float4 kv = *(const float4*)(Kb + r * HDm + c);
            Kst[(c + 0) * PITCH + r] = kv.x;
            Kst[(c + 1) * PITCH + r] = kv.y;
            Kst[(c + 2) * PITCH + r] = kv.z;
            Kst[(c + 3) * PITCH + r] = kv.w;
            float4 vv = *(const float4*)(Vb + r * HDm + c);
            *(float4*)&Vs[r * PITCH + c] = vv;
        }
        __syncthreads();

        // S = Q @ K^T (per-thread 4x4)
        float sacc[4][4];
#pragma unroll
        for (int i = 0; i < 4; i++)
#pragma unroll
            for (int j = 0; j < 4; j++) sacc[i][j] = 0.f;

#pragma unroll 16
        for (int kd = 0; kd < 64; kd++) {
            float4 qf = *(const float4*)&Qst[kd * PITCH + ty * 4];
            float4 kf = *(const float4*)&Kst[kd * PITCH + tx * 4];
            const float qa[4] = {qf.x, qf.y, qf.z, qf.w};
            const float ka[4] = {kf.x, kf.y, kf.z, kf.w};
#pragma unroll
            for (int i = 0; i < 4; i++)
#pragma unroll
                for (int j = 0; j < 4; j++)
                    sacc[i][j] = fmaf(qa[i], ka[j], sacc[i][j]);
        }

        // Online softmax (rows distributed over 16-lane groups)
#pragma unroll
        for (int i = 0; i < 4; i++) {
            const int qg = q0 + ty * 4 + i;
            float sv[4];
            float rowmax = -1e30f;
#pragma unroll
            for (int j = 0; j < 4; j++) {
                const int jg = kb * 64 + tx * 4 + j;
                const int d  = qg - jg;
                const bool valid = (d >= 0) && (d < WIN);
                sv[j] = valid ? sacc[i][j] * 0.125f : -1e30f;
                rowmax = fmaxf(rowmax, sv[j]);
            }
#pragma unroll
            for (int off = 8; off > 0; off >>= 1)
                rowmax = fmaxf(rowmax, __shfl_xor_sync(0xffffffffu, rowmax, off));
            const float mn = fmaxf(m_prev[i], rowmax);
            float psum = 0.f;
#pragma unroll
            for (int j = 0; j < 4; j++) {
                const float p = (sv[j] > -1e29f) ? __expf(sv[j] - mn) : 0.f;
                psum += p;
                Pst[(tx * 4 + j) * PITCH + ty * 4 + i] = p;   // k-major
            }
#pragma unroll
            for (int off = 8; off > 0; off >>= 1)
                psum += __shfl_xor_sync(0xffffffffu, psum, off);
            const float corr = __expf(m_prev[i] - mn);  // underflows to 0 when m_prev=-1e30
            lsum[i] = lsum[i] * corr + psum;
            m_prev[i] = mn;
#pragma unroll
            for (int j = 0; j < 4; j++) o[i][j] *= corr;
        }
        __syncthreads();

        // O += P @ V
#pragma unroll 16
        for (int k = 0; k < 64; k++) {
            float4 pf = *(const float4*)&Pst[k * PITCH + ty * 4];
            float4 vf = *(const float4*)&Vs[k * PITCH + tx * 4];
            const float pa[4] = {pf.x, pf.y, pf.z, pf.w};
            const float va[4] = {vf.x, vf.y, vf.z, vf.w};
#pragma unroll
            for (int i = 0; i < 4; i++)
#pragma unroll
                for (int j = 0; j < 4; j++)
                    o[i][j] = fmaf(pa[i], va[j], o[i][j]);
        }
        __syncthreads();
    }

    // Normalize + store to attention output scratch in (b, s, h*hd) layout
#pragma unroll
    for (int i = 0; i < 4; i++) {
        const int qg = q0 + ty * 4 + i;
        const float inv = 1.f / lsum[i];
        float4 v;
        v.x = o[i][0] * inv; v.y = o[i][1] * inv;
        v.z = o[i][2] * inv; v.w = o[i][3] * inv;
        *(float4*)&g_AO[(size_t)(b * SS + qg) * DM + h * HDm + tx * 4] = v;
    }
}

// ---------------------------------------------------------------------------
extern "C" void kernel_launch(void* const* d_in, const int* in_sizes, int n_in,
                              void* d_out, int out_size)
{
    const float* x     = (const float*)d_in[0];
    const float* qkvw  = (const float*)d_in[1];
    const float* qkvb  = (const float*)d_in[2];
    const float* outw  = (const float*)d_in[3];
    const float* outb  = (const float*)d_in[4];
    float* out = (float*)d_out;

    // Opt in to >48KB dynamic smem for the attention kernel. Idempotent; the
    // attribute set during the correctness run persists for the capture run.
    cudaFuncSetAttribute(attn_kernel, cudaFuncAttributeMaxDynamicSharedMemorySize,
                         ATTN_SMEM_BYTES);

    // 1) QKV projection (scatter into Q/K/V scratch)
    gemm_kernel<ND3, 0><<<dim3(ND3 / 128, MT / 128), 256>>>(x, qkvw, qkvb, nullptr);

    // 2) Windowed attention
    attn_kernel<<<dim3(SS / 64, NH, BB), 256, ATTN_SMEM_BYTES>>>();

    // 3) Output projection
    gemm_kernel<DM, 1><<<dim3(DM / 128, MT / 128), 256>>>(nullptr, outw, outb, out);
}

// round 7
// speedup vs baseline: 1.0996x; 1.0996x over previous
#include <cuda_runtime.h>

// ---------------------------------------------------------------------------
// SlidingWindowAttention: x->QKV proj -> windowed attention -> out proj
// B=2, S=2048, H=16, hd=64, D=1024, window=512. All fp32.
// R6: double-buffered GEMMs (1 sync/tile, prefetch regs), double-buffered
//     K/V in attention, prescaled Q, full-block mask skip.
// ---------------------------------------------------------------------------

constexpr int BB  = 2;
constexpr int SS  = 2048;
constexpr int NH  = 16;
constexpr int HDm = 64;
constexpr int DM  = 1024;      // NH*HDm
constexpr int ND3 = 3072;      // 3*DM
constexpr int WIN = 512;
constexpr int MT  = BB * SS;   // 4096 rows

// Scratch (device globals: allocation-free)
__device__ float g_Q[BB * NH * SS * HDm];
__device__ float g_K[BB * NH * SS * HDm];
__device__ float g_V[BB * NH * SS * HDm];
__device__ float g_AO[BB * SS * DM];

// ---------------------------------------------------------------------------
// SGEMM: C[M=4096][N] = A[4096][1024] @ W[1024][N] + bias
// BM=BN=128, BK=8, 256 threads, 8x8 micro-tile, double-buffered smem.
// EPI==0: A = x param, scatter into g_Q/g_K/g_V (layout (b,h,s,d))
// EPI==1: A = g_AO, plain write to Cout + bias
// ---------------------------------------------------------------------------
template <int N, int EPI>
__global__ __launch_bounds__(256) void gemm_kernel(const float* __restrict__ A,
                                                   const float* __restrict__ Bmat,
                                                   const float* __restrict__ bias,
                                                   float* __restrict__ Cout)
{
    __shared__ float As[2][8][132];   // transposed A tile, padded
    __shared__ float Bs[2][8][128];

    const int tid = threadIdx.x;
    const int n0  = blockIdx.x * 128;
    const int m0  = blockIdx.y * 128;
    const int ty  = tid >> 4;          // 0..15 -> M rows ty*8..+7
    const int tx  = tid & 15;          // 0..15 -> N cols tx*8..+7
    const int arow = tid >> 1;         // 0..127
    const int acol = (tid & 1) * 4;    // 0 or 4
    const int brow = tid >> 5;         // 0..7
    const int bcol = (tid & 31) * 4;   // 0..124

    const float* Ap = (EPI == 0) ? A : g_AO;

    float acc[8][8];
#pragma unroll
    for (int i = 0; i < 8; i++)
#pragma unroll
        for (int j = 0; j < 8; j++) acc[i][j] = 0.f;

    const float* aptr = Ap + (m0 + arow) * DM + acol;
    const float* bptr = Bmat + brow * N + n0 + bcol;

    // Prologue: fill buffer 0
    {
        float4 a4 = *(const float4*)(aptr);
        float4 b4 = *(const float4*)(bptr);
        As[0][acol + 0][arow] = a4.x;
        As[0][acol + 1][arow] = a4.y;
        As[0][acol + 2][arow] = a4.z;
        As[0][acol + 3][arow] = a4.w;
        *(float4*)&Bs[0][brow][bcol] = b4;
    }
    __syncthreads();

    int buf = 0;
    for (int k0 = 8; k0 < DM; k0 += 8) {
        // Prefetch next tile into registers (latency hidden by compute below)
        float4 an = *(const float4*)(aptr + k0);
        float4 bn = *(const float4*)(bptr + k0 * N);

#pragma unroll
        for (int k = 0; k < 8; k++) {
            float af[8], bf[8];
            *(float4*)&af[0] = *(const float4*)&As[buf][k][ty * 8];
            *(float4*)&af[4] = *(const float4*)&As[buf][k][ty * 8 + 4];
            *(float4*)&bf[0] = *(const float4*)&Bs[buf][k][tx * 8];
            *(float4*)&bf[4] = *(const float4*)&Bs[buf][k][tx * 8 + 4];
#pragma unroll
            for (int i = 0; i < 8; i++)
#pragma unroll
                for (int j = 0; j < 8; j++)
                    acc[i][j] = fmaf(af[i], bf[j], acc[i][j]);
        }

        const int nb = buf ^ 1;
        As[nb][acol + 0][arow] = an.x;
        As[nb][acol + 1][arow] = an.y;
        As[nb][acol + 2][arow] = an.z;
        As[nb][acol + 3][arow] = an.w;
        *(float4*)&Bs[nb][brow][bcol] = bn;
        __syncthreads();
        buf = nb;
    }

    // Final tile compute
#pragma unroll
    for (int k = 0; k < 8; k++) {
        float af[8], bf[8];
        *(float4*)&af[0] = *(const float4*)&As[buf][k][ty * 8];
        *(float4*)&af[4] = *(const float4*)&As[buf][k][ty * 8 + 4];
        *(float4*)&bf[0] = *(const float4*)&Bs[buf][k][tx * 8];
        *(float4*)&bf[4] = *(const float4*)&Bs[buf][k][tx * 8 + 4];
#pragma unroll
        for (int i = 0; i < 8; i++)
#pragma unroll
            for (int j = 0; j < 8; j++)
                acc[i][j] = fmaf(af[i], bf[j], acc[i][j]);
    }

    if (EPI == 0) {
        // n0 multiple of 128, 1024%128==0 -> 'which' uniform per CTA
        const int which = n0 >> 10;
        float* dst = (which == 0) ? g_Q : (which == 1) ? g_K : g_V;
        const int n_base = n0 + tx * 8;       // stays inside one head
        const int rem = n_base & (DM - 1);
        const int hh  = rem >> 6;
        const int d0  = rem & 63;
#pragma unroll
        for (int i = 0; i < 8; i++) {
            const int m  = m0 + ty * 8 + i;
            const int bb = m >> 11;           // /SS
            const int ss = m & (SS - 1);
            float* row = dst + ((bb * NH + hh) * SS + ss) * HDm + d0;
#pragma unroll
            for (int j = 0; j < 8; j++)
                row[j] = acc[i][j] + bias[n_base + j];
        }
    } else {
        const int n_base = n0 + tx * 8;
        float bv[8];
#pragma unroll
        for (int j = 0; j < 8; j++) bv[j] = bias[n_base + j];
#pragma unroll
        for (int i = 0; i < 8; i++) {
            const int m = m0 + ty * 8 + i;
            float4 v0, v1;
            v0.x = acc[i][0] + bv[0]; v0.y = acc[i][1] + bv[1];
            v0.z = acc[i][2] + bv[2]; v0.w = acc[i][3] + bv[3];
            v1.x = acc[i][4] + bv[4]; v1.y = acc[i][5] + bv[5];
            v1.z = acc[i][6] + bv[6]; v1.w = acc[i][7] + bv[7];
            *(float4*)&Cout[m * N + n_base]     = v0;
            *(float4*)&Cout[m * N + n_base + 4] = v1;
        }
    }
}

// ---------------------------------------------------------------------------
// Windowed flash attention. One CTA per (64-query tile, head, batch).
// 256 threads = 16x16; each thread owns 4q x 4col.
// Double-buffered K/V; Q prescaled by 1/8.
// Smem: Qst | Kst0 | Vs0 | Kst1 | Vs1 | Pst (each 64 x PITCH floats)
// ---------------------------------------------------------------------------
constexpr int PITCH = 68;
constexpr int TSZ = 64 * PITCH;
constexpr int ATTN_SMEM_BYTES = 6 * TSZ * (int)sizeof(float);  // 104448

__device__ __forceinline__ void load_kv(const float* __restrict__ Kb,
                                        const float* __restrict__ Vb,
                                        float* __restrict__ Kst,
                                        float* __restrict__ Vs,
                                        int tid)
{
#pragma unroll
    for (int it = 0; it < 4; it++) {
        const int t = tid + it * 256;
        const int r = t >> 4;
        const int c = (t & 15) * 4;
        float4 kv = *(const float4*)(Kb + r * HDm + c);
        Kst[(c + 0) * PITCH + r] = kv.x;
        Kst[(c + 1) * PITCH + r] = kv.y;
        Kst[(c + 2) * PITCH + r] = kv.z;
        Kst[(c + 3) * PITCH + r] = kv.w;
        float4 vv = *(const float4*)(Vb + r * HDm + c);
        *(float4*)&Vs[r * PITCH + c] = vv;
    }
}

__global__ __launch_bounds__(256) void attn_kernel()
{
    extern __shared__ float smf[];
    float* Qst = smf;                       // [kd][q]
    float* Pst = smf + 5 * TSZ;             // [k][q]

    const int tid = threadIdx.x;
    const int ty  = tid >> 4;     // rows ty*4..+3
    const int tx  = tid & 15;     // cols tx*4..+3
    const int q0  = blockIdx.x * 64;
    const int h   = blockIdx.y;
    const int b   = blockIdx.z;

    const float* Qg = g_Q + (size_t)(b * NH + h) * SS * HDm;
    const float* Kg = g_K + (size_t)(b * NH + h) * SS * HDm;
    const float* Vg = g_V + (size_t)(b * NH + h) * SS * HDm;

    // Load Q tile (64 x 64) transposed to kd-major, prescaled by 1/sqrt(hd)
#pragma unroll
    for (int it = 0; it < 4; it++) {
        const int t = tid + it * 256;
        const int r = t >> 4;
        const int c = (t & 15) * 4;
        float4 v = *(const float4*)(Qg + (q0 + r) * HDm + c);
        Qst[(c + 0) * PITCH + r] = v.x * 0.125f;
        Qst[(c + 1) * PITCH + r] = v.y * 0.125f;
        Qst[(c + 2) * PITCH + r] = v.z * 0.125f;
        Qst[(c + 3) * PITCH + r] = v.w * 0.125f;
    }

    float m_prev[4], lsum[4], o[4][4];
#pragma unroll
    for (int i = 0; i < 4; i++) {
        m_prev[i] = -1e30f;
        lsum[i] = 0.f;
#pragma unroll
        for (int j = 0; j < 4; j++) o[i][j] = 0.f;
    }

    const int kb_start = (q0 >= WIN) ? ((q0 - (WIN - 1)) >> 6) : 0;
    const int kb_end   = q0 >> 6;    // inclusive

    // Prologue: fill buffer 0 with first K/V block
    load_kv(Kg + kb_start * 64 * HDm, Vg + kb_start * 64 * HDm,
            smf + 1 * TSZ, smf + 2 * TSZ, tid);
    __syncthreads();

    int buf = 0;
    for (int kb = kb_start; kb <= kb_end; kb++) {
        float* Kst = smf + (1 + 2 * buf) * TSZ;
        float* Vs  = Kst + TSZ;

        // Prefetch next K/V block into the other buffer (consumed next iter)
        if (kb < kb_end) {
            float* Kn = smf + (1 + 2 * (buf ^ 1)) * TSZ;
            load_kv(Kg + (kb + 1) * 64 * HDm, Vg + (kb + 1) * 64 * HDm,
                    Kn, Kn + TSZ, tid);
        }

        // S = Q @ K^T (per-thread 4x4), scale already folded into Q
        float sacc[4][4];
#pragma unroll
        for (int i = 0; i < 4; i++)
#pragma unroll
            for (int j = 0; j < 4; j++) sacc[i][j] = 0.f;

#pragma unroll 16
        for (int kd = 0; kd < 64; kd++) {
            float4 qf = *(const float4*)&Qst[kd * PITCH + ty * 4];
            float4 kf = *(const float4*)&Kst[kd * PITCH + tx * 4];
            const float qa[4] = {qf.x, qf.y, qf.z, qf.w};
            const float ka[4] = {kf.x, kf.y, kf.z, kf.w};
#pragma unroll
            for (int i = 0; i < 4; i++)
#pragma unroll
                for (int j = 0; j < 4; j++)
                    sacc[i][j] = fmaf(qa[i], ka[j], sacc[i][j]);
        }

        // Is this key block fully inside the window for every (q, j) pair?
        const int diff = q0 - kb * 64;
        const bool full = (diff >= 63) && (diff + 63 < WIN);

        // Online softmax (rows distributed over 16-lane groups)
#pragma unroll
        for (int i = 0; i < 4; i++) {
            float sv[4];
            float rowmax = -1e30f;
            if (full) {
#pragma unroll
                for (int j = 0; j < 4; j++) {
                    sv[j] = sacc[i][j];
                    rowmax = fmaxf(rowmax, sv[j]);
                }
            } else {
                const int qg = q0 + ty * 4 + i;
#pragma unroll
                for (int j = 0; j < 4; j++) {
                    const int jg = kb * 64 + tx * 4 + j;
                    const int d  = qg - jg;
                    const bool valid = (d >= 0) && (d < WIN);
                    sv[j] = valid ? sacc[i][j] : -1e30f;
                    rowmax = fmaxf(rowmax, sv[j]);
                }
            }
#pragma unroll
            for (int off = 8; off > 0; off >>= 1)
                rowmax = fmaxf(rowmax, __shfl_xor_sync(0xffffffffu, rowmax, off));
            const float mn = fmaxf(m_prev[i], rowmax);
            float psum = 0.f;
#pragma unroll
            for (int j = 0; j < 4; j++) {
                const float p = (sv[j] > -1e29f) ? __expf(sv[j] - mn) : 0.f;
                psum += p;
                Pst[(tx * 4 + j) * PITCH + ty * 4 + i] = p;   // k-major
            }
#pragma unroll
            for (int off = 8; off > 0; off >>= 1)
                psum += __shfl_xor_sync(0xffffffffu, psum, off);
            const float corr = __expf(m_prev[i] - mn);  // 0 on first block
            lsum[i] = lsum[i] * corr + psum;
            m_prev[i] = mn;
#pragma unroll
            for (int j = 0; j < 4; j++) o[i][j] *= corr;
        }
        __syncthreads();

        // O += P @ V
#pragma unroll 16
        for (int k = 0; k < 64; k++) {
            float4 pf = *(const float4*)&Pst[k * PITCH + ty * 4];
            float4 vf = *(const float4*)&Vs[k * PITCH + tx * 4];
            const float pa[4] = {pf.x, pf.y, pf.z, pf.w};
            const float va[4] = {vf.x, vf.y, vf.z, vf.w};
#pragma unroll
            for (int i = 0; i < 4; i++)
#pragma unroll
                for (int j = 0; j < 4; j++)
                    o[i][j] = fmaf(pa[i], va[j], o[i][j]);
        }
        __syncthreads();
        buf ^= 1;
    }

    // Normalize + store to attention scratch in (b, s, h*hd) layout
#pragma unroll
    for (int i = 0; i < 4; i++) {
        const int qg = q0 + ty * 4 + i;
        const float inv = 1.f / lsum[i];
        float4 v;
        v.x = o[i][0] * inv; v.y = o[i][1] * inv;
        v.z = o[i][2] * inv; v.w = o[i][3] * inv;
        *(float4*)&g_AO[(size_t)(b * SS + qg) * DM + h * HDm + tx * 4] = v;
    }
}

// ---------------------------------------------------------------------------
extern "C" void kernel_launch(void* const* d_in, const int* in_sizes, int n_in,
                              void* d_out, int out_size)
{
    const float* x     = (const float*)d_in[0];
    const float* qkvw  = (const float*)d_in[1];
    const float* qkvb  = (const float*)d_in[2];
    const float* outw  = (const float*)d_in[3];
    const float* outb  = (const float*)d_in[4];
    float* out = (float*)d_out;

    cudaFuncSetAttribute(attn_kernel, cudaFuncAttributeMaxDynamicSharedMemorySize,
                         ATTN_SMEM_BYTES);

    // 1) QKV projection (scatter into Q/K/V scratch)
    gemm_kernel<ND3, 0><<<dim3(ND3 / 128, MT / 128), 256>>>(x, qkvw, qkvb, nullptr);

    // 2) Windowed attention
    attn_kernel<<<dim3(SS / 64, NH, BB), 256, ATTN_SMEM_BYTES>>>();

    // 3) Output projection
    gemm_kernel<DM, 1><<<dim3(DM / 128, MT / 128), 256>>>(nullptr, outw, outb, out);
}

// round 8
// speedup vs baseline: 1.1024x; 1.0026x over previous
#include <cuda_runtime.h>

// ---------------------------------------------------------------------------
// SlidingWindowAttention: x->QKV proj -> windowed attention -> out proj
// B=2, S=2048, H=16, hd=64, D=1024, window=512. All fp32.
// R6: double-buffered GEMMs (1 sync/tile, prefetch regs), double-buffered
//     K/V in attention, prescaled Q, full-block mask skip.
// ---------------------------------------------------------------------------

constexpr int BB  = 2;
constexpr int SS  = 2048;
constexpr int NH  = 16;
constexpr int HDm = 64;
constexpr int DM  = 1024;      // NH*HDm
constexpr int ND3 = 3072;      // 3*DM
constexpr int WIN = 512;
constexpr int MT  = BB * SS;   // 4096 rows

// Scratch (device globals: allocation-free)
__device__ float g_Q[BB * NH * SS * HDm];
__device__ float g_K[BB * NH * SS * HDm];
__device__ float g_V[BB * NH * SS * HDm];
__device__ float g_AO[BB * SS * DM];

// ---------------------------------------------------------------------------
// SGEMM: C[M=4096][N] = A[4096][1024] @ W[1024][N] + bias
// BM=BN=128, BK=8, 256 threads, 8x8 micro-tile, double-buffered smem.
// EPI==0: A = x param, scatter into g_Q/g_K/g_V (layout (b,h,s,d))
// EPI==1: A = g_AO, plain write to Cout + bias
// ---------------------------------------------------------------------------
template <int N, int EPI>
__global__ __launch_bounds__(256) void gemm_kernel(const float* __restrict__ A,
                                                   const float* __restrict__ Bmat,
                                                   const float* __restrict__ bias,
                                                   float* __restrict__ Cout)
{
    __shared__ float As[2][8][132];   // transposed A tile, padded
    __shared__ float Bs[2][8][128];

    const int tid = threadIdx.x;
    const int n0  = blockIdx.x * 128;
    const int m0  = blockIdx.y * 128;
    const int ty  = tid >> 4;          // 0..15 -> M rows ty*8..+7
    const int tx  = tid & 15;          // 0..15 -> N cols tx*8..+7
    const int arow = tid >> 1;         // 0..127
    const int acol = (tid & 1) * 4;    // 0 or 4
    const int brow = tid >> 5;         // 0..7
    const int bcol = (tid & 31) * 4;   // 0..124

    const float* Ap = (EPI == 0) ? A : g_AO;

    float acc[8][8];
#pragma unroll
    for (int i = 0; i < 8; i++)
#pragma unroll
        for (int j = 0; j < 8; j++) acc[i][j] = 0.f;

    const float* aptr = Ap + (m0 + arow) * DM + acol;
    const float* bptr = Bmat + brow * N + n0 + bcol;

    // Prologue: fill buffer 0
    {
        float4 a4 = *(const float4*)(aptr);
        float4 b4 = *(const float4*)(bptr);
        As[0][acol + 0][arow] = a4.x;
        As[0][acol + 1][arow] = a4.y;
        As[0][acol + 2][arow] = a4.z;
        As[0][acol + 3][arow] = a4.w;
        *(float4*)&Bs[0][brow][bcol] = b4;
    }
    __syncthreads();

    int buf = 0;
    for (int k0 = 8; k0 < DM; k0 += 8) {
        // Prefetch next tile into registers (latency hidden by compute below)
        float4 an = *(const float4*)(aptr + k0);
        float4 bn = *(const float4*)(bptr + k0 * N);

#pragma unroll
        for (int k = 0; k < 8; k++) {
            float af[8], bf[8];
            *(float4*)&af[0] = *(const float4*)&As[buf][k][ty * 8];
            *(float4*)&af[4] = *(const float4*)&As[buf][k][ty * 8 + 4];
            *(float4*)&bf[0] = *(const float4*)&Bs[buf][k][tx * 8];
            *(float4*)&bf[4] = *(const float4*)&Bs[buf][k][tx * 8 + 4];
#pragma unroll
            for (int i = 0; i < 8; i++)
#pragma unroll
                for (int j = 0; j < 8; j++)
                    acc[i][j] = fmaf(af[i], bf[j], acc[i][j]);
        }

        const int nb = buf ^ 1;
        As[nb][acol + 0][arow] = an.x;
        As[nb][acol + 1][arow] = an.y;
        As[nb][acol + 2][arow] = an.z;
        As[nb][acol + 3][arow] = an.w;
        *(float4*)&Bs[nb][brow][bcol] = bn;
        __syncthreads();
        buf = nb;
    }

    // Final tile compute
#pragma unroll
    for (int k = 0; k < 8; k++) {
        float af[8], bf[8];
        *(float4*)&af[0] = *(const float4*)&As[buf][k][ty * 8];
        *(float4*)&af[4] = *(const float4*)&As[buf][k][ty * 8 + 4];
        *(float4*)&bf[0] = *(const float4*)&Bs[buf][k][tx * 8];
        *(float4*)&bf[4] = *(const float4*)&Bs[buf][k][tx * 8 + 4];
#pragma unroll
        for (int i = 0; i < 8; i++)
#pragma unroll
            for (int j = 0; j < 8; j++)
                acc[i][j] = fmaf(af[i], bf[j], acc[i][j]);
    }

    if (EPI == 0) {
        // n0 multiple of 128, 1024%128==0 -> 'which' uniform per CTA
        const int which = n0 >> 10;
        float* dst = (which == 0) ? g_Q : (which == 1) ? g_K : g_V;
        const int n_base = n0 + tx * 8;       // stays inside one head
        const int rem = n_base & (DM - 1);
        const int hh  = rem >> 6;
        const int d0  = rem & 63;
#pragma unroll
        for (int i = 0; i < 8; i++) {
            const int m  = m0 + ty * 8 + i;
            const int bb = m >> 11;           // /SS
            const int ss = m & (SS - 1);
            float* row = dst + ((bb * NH + hh) * SS + ss) * HDm + d0;
#pragma unroll
            for (int j = 0; j < 8; j++)
                row[j] = acc[i][j] + bias[n_base + j];
        }
    } else {
        const int n_base = n0 + tx * 8;
        float bv[8];
#pragma unroll
        for (int j = 0; j < 8; j++) bv[j] = bias[n_base + j];
#pragma unroll
        for (int i = 0; i < 8; i++) {
            const int m = m0 + ty * 8 + i;
            float4 v0, v1;
            v0.x = acc[i][0] + bv[0]; v0.y = acc[i][1] + bv[1];
            v0.z = acc[i][2] + bv[2]; v0.w = acc[i][3] + bv[3];
            v1.x = acc[i][4] + bv[4]; v1.y = acc[i][5] + bv[5];
            v1.z = acc[i][6] + bv[6]; v1.w = acc[i][7] + bv[7];
            *(float4*)&Cout[m * N + n_base]     = v0;
            *(float4*)&Cout[m * N + n_base + 4] = v1;
        }
    }
}

// ---------------------------------------------------------------------------
// Windowed flash attention. One CTA per (64-query tile, head, batch).
// 256 threads = 16x16; each thread owns 4q x 4col.
// Double-buffered K/V; Q prescaled by 1/8.
// Smem: Qst | Kst0 | Vs0 | Kst1 | Vs1 | Pst (each 64 x PITCH floats)
// ---------------------------------------------------------------------------
constexpr int PITCH = 68;
constexpr int TSZ = 64 * PITCH;
constexpr int ATTN_SMEM_BYTES = 6 * TSZ * (int)sizeof(float);  // 104448

__device__ __forceinline__ void load_kv(const float* __restrict__ Kb,
                                        const float* __restrict__ Vb,
                                        float* __restrict__ Kst,
                                        float* __restrict__ Vs,
                                        int tid)
{
#pragma unroll
    for (int it = 0; it < 4; it++) {
        const int t = tid + it * 256;
        const int r = t >> 4;
        const int c = (t & 15) * 4;
        float4 kv = *(const float4*)(Kb + r * HDm + c);
        Kst[(c + 0) * PITCH + r] = kv.x;
        Kst[(c + 1) * PITCH + r] = kv.y;
        Kst[(c + 2) * PITCH + r] = kv.z;
        Kst[(c + 3) * PITCH + r] = kv.w;
        float4 vv = *(const float4*)(Vb + r * HDm + c);
        *(float4*)&Vs[r * PITCH + c] = vv;
    }
}

__global__ __launch_bounds__(256) void attn_kernel()
{
    extern __shared__ float smf[];
    float* Qst = smf;                       // [kd][q]
    float* Pst = smf + 5 * TSZ;             // [k][q]

    const int tid = threadIdx.x;
    const int ty  = tid >> 4;     // rows ty*4..+3
    const int tx  = tid & 15;     // cols tx*4..+3
    const int q0  = blockIdx.x * 64;
    const int h   = blockIdx.y;
    const int b   = blockIdx.z;

    const float* Qg = g_Q + (size_t)(b * NH + h) * SS * HDm;
    const float* Kg = g_K + (size_t)(b * NH + h) * SS * HDm;
    const float* Vg = g_V + (size_t)(b * NH + h) * SS * HDm;

    // Load Q tile (64 x 64) transposed to kd-major, prescaled by 1/sqrt(hd)
#pragma unroll
    for (int it = 0; it < 4; it++) {
        const int t = tid + it * 256;
        const int r = t >> 4;
        const int c = (t & 15) * 4;
        float4 v = *(const float4*)(Qg + (q0 + r) * HDm + c);
        Qst[(c + 0) * PITCH + r] = v.x * 0.125f;
        Qst[(c + 1) * PITCH + r] = v.y * 0.125f;
        Qst[(c + 2) * PITCH + r] = v.z * 0.125f;
        Qst[(c + 3) * PITCH + r] = v.w * 0.125f;
    }

    float m_prev[4], lsum[4], o[4][4];
#pragma unroll
    for (int i = 0; i < 4; i++) {
        m_prev[i] = -1e30f;
        lsum[i] = 0.f;
#pragma unroll
        for (int j = 0; j < 4; j++) o[i][j] = 0.f;
    }

    const int kb_start = (q0 >= WIN) ? ((q0 - (WIN - 1)) >> 6) : 0;
    const int kb_end   = q0 >> 6;    // inclusive

    // Prologue: fill buffer 0 with first K/V block
    load_kv(Kg + kb_start * 64 * HDm, Vg + kb_start * 64 * HDm,
            smf + 1 * TSZ, smf + 2 * TSZ, tid);
    __syncthreads();

    int buf = 0;
    for (int kb = kb_start; kb <= kb_end; kb++) {
        float* Kst = smf + (1 + 2 * buf) * TSZ;
        float* Vs  = Kst + TSZ;

        // Prefetch next K/V block into the other buffer (consumed next iter)
        if (kb < kb_end) {
            float* Kn = smf + (1 + 2 * (buf ^ 1)) * TSZ;
            load_kv(Kg + (kb + 1) * 64 * HDm, Vg + (kb + 1) * 64 * HDm,
                    Kn, Kn + TSZ, tid);
        }

        // S = Q @ K^T (per-thread 4x4), scale already folded into Q
        float sacc[4][4];
#pragma unroll
        for (int i = 0; i < 4; i++)
#pragma unroll
            for (int j = 0; j < 4; j++) sacc[i][j] = 0.f;

#pragma unroll 16
        for (int kd = 0; kd < 64; kd++) {
            float4 qf = *(const float4*)&Qst[kd * PITCH + ty * 4];
            float4 kf = *(const float4*)&Kst[kd * PITCH + tx * 4];
            const float qa[4] = {qf.x, qf.y, qf.z, qf.w};
            const float ka[4] = {kf.x, kf.y, kf.z, kf.w};
#pragma unroll
            for (int i = 0; i < 4; i++)
#pragma unroll
                for (int j = 0; j < 4; j++)
                    sacc[i][j] = fmaf(qa[i], ka[j], sacc[i][j]);
        }

        // Is this key block fully inside the window for every (q, j) pair?
        const int diff = q0 - kb * 64;
        const bool full = (diff >= 63) && (diff + 63 < WIN);

        // Online softmax (rows distributed over 16-lane groups)
#pragma unroll
        for (int i = 0; i < 4; i++) {
            float sv[4];
            float rowmax = -1e30f;
            if (full) {
#pragma unroll
                for (int j = 0; j < 4; j++) {
                    sv[j] = sacc[i][j];
                    rowmax = fmaxf(rowmax, sv[j]);
                }
            } else {
                const int qg = q0 + ty * 4 + i;
#pragma unroll
                for (int j = 0; j < 4; j++) {
                    const int jg = kb * 64 + tx * 4 + j;
                    const int d  = qg - jg;
                    const bool valid = (d >= 0) && (d < WIN);
                    sv[j] = valid ? sacc[i][j] : -1e30f;
                    rowmax = fmaxf(rowmax, sv[j]);
                }
            }
#pragma unroll
            for (int off = 8; off > 0; off >>= 1)
                rowmax = fmaxf(rowmax, __shfl_xor_sync(0xffffffffu, rowmax, off));
            const float mn = fmaxf(m_prev[i], rowmax);
            float psum = 0.f;
#pragma unroll
            for (int j = 0; j < 4; j++) {
                const float p = (sv[j] > -1e29f) ? __expf(sv[j] - mn) : 0.f;
                psum += p;
                Pst[(tx * 4 + j) * PITCH + ty * 4 + i] = p;   // k-major
            }
#pragma unroll
            for (int off = 8; off > 0; off >>= 1)
                psum += __shfl_xor_sync(0xffffffffu, psum, off);
            const float corr = __expf(m_prev[i] - mn);  // 0 on first block
            lsum[i] = lsum[i] * corr + psum;
            m_prev[i] = mn;
#pragma unroll
            for (int j = 0; j < 4; j++) o[i][j] *= corr;
        }
        __syncthreads();

        // O += P @ V
#pragma unroll 16
        for (int k = 0; k < 64; k++) {
            float4 pf = *(const float4*)&Pst[k * PITCH + ty * 4];
            float4 vf = *(const float4*)&Vs[k * PITCH + tx * 4];
            const float pa[4] = {pf.x, pf.y, pf.z, pf.w};
            const float va[4] = {vf.x, vf.y, vf.z, vf.w};
#pragma unroll
            for (int i = 0; i < 4; i++)
#pragma unroll
                for (int j = 0; j < 4; j++)
                    o[i][j] = fmaf(pa[i], va[j], o[i][j]);
        }
        __syncthreads();
        buf ^= 1;
    }

    // Normalize + store to attention scratch in (b, s, h*hd) layout
#pragma unroll
    for (int i = 0; i < 4; i++) {
        const int qg = q0 + ty * 4 + i;
        const float inv = 1.f / lsum[i];
        float4 v;
        v.x = o[i][0] * inv; v.y = o[i][1] * inv;
        v.z = o[i][2] * inv; v.w = o[i][3] * inv;
        *(float4*)&g_AO[(size_t)(b * SS + qg) * DM + h * HDm + tx * 4] = v;
    }
}

// ---------------------------------------------------------------------------
extern "C" void kernel_launch(void* const* d_in, const int* in_sizes, int n_in,
                              void* d_out, int out_size)
{
    const float* x     = (const float*)d_in[0];
    const float* qkvw  = (const float*)d_in[1];
    const float* qkvb  = (const float*)d_in[2];
    const float* outw  = (const float*)d_in[3];
    const float* outb  = (const float*)d_in[4];
    float* out = (float*)d_out;

    cudaFuncSetAttribute(attn_kernel, cudaFuncAttributeMaxDynamicSharedMemorySize,
                         ATTN_SMEM_BYTES);

    // 1) QKV projection (scatter into Q/K/V scratch)
    gemm_kernel<ND3, 0><<<dim3(ND3 / 128, MT / 128), 256>>>(x, qkvw, qkvb, nullptr);

    // 2) Windowed attention
    attn_kernel<<<dim3(SS / 64, NH, BB), 256, ATTN_SMEM_BYTES>>>();

    // 3) Output projection
    gemm_kernel<DM, 1><<<dim3(DM / 128, MT / 128), 256>>>(nullptr, outw, outb, out);
}